// round 3
// baseline (speedup 1.0000x reference)
#include <cuda_runtime.h>

// Geometric product for Cl(3,0,0), blades in short-lex order:
//   idx: 0=1, 1=e1, 2=e2, 3=e3, 4=e12, 5=e13, 6=e23, 7=e123
// out_j = sum_{i,k} a_i * C[i,j,k] * b_k, with C the (fixed) Euclidean Cayley
// table — 64 nonzeros, signs hardcoded below (derived from the reference's
// _construct_cayley with METRIC=[1,1,1]). The cayley input buffer is ignored.

__global__ void __launch_bounds__(256)
clifford_gp_kernel(const float4* __restrict__ a4,
                   const float4* __restrict__ b4,
                   float4* __restrict__ out4,
                   int n_mv)
{
    int t = blockIdx.x * blockDim.x + threadIdx.x;
    if (t >= n_mv) return;

    // Each multivector = 8 floats = 2 float4s. Issue all 4 loads up front (MLP=4).
    float4 al = a4[2 * t + 0];
    float4 ah = a4[2 * t + 1];
    float4 bl = b4[2 * t + 0];
    float4 bh = b4[2 * t + 1];

    float A0 = al.x, A1 = al.y, A2 = al.z, A3 = al.w;
    float A4 = ah.x, A5 = ah.y, A6 = ah.z, A7 = ah.w;
    float B0 = bl.x, B1 = bl.y, B2 = bl.z, B3 = bl.w;
    float B4 = bh.x, B5 = bh.y, B6 = bh.z, B7 = bh.w;

    // scalar
    float o0 = A0*B0 + A1*B1 + A2*B2 + A3*B3 - A4*B4 - A5*B5 - A6*B6 - A7*B7;
    // e1
    float o1 = A0*B1 + A1*B0 - A2*B4 + A4*B2 - A3*B5 + A5*B3 - A6*B7 - A7*B6;
    // e2
    float o2 = A0*B2 + A2*B0 + A1*B4 - A4*B1 - A3*B6 + A6*B3 + A5*B7 + A7*B5;
    // e3
    float o3 = A0*B3 + A3*B0 + A1*B5 - A5*B1 + A2*B6 - A6*B2 - A4*B7 - A7*B4;
    // e12
    float o4v = A0*B4 + A4*B0 + A1*B2 - A2*B1 + A3*B7 + A7*B3 - A5*B6 + A6*B5;
    // e13
    float o5 = A0*B5 + A5*B0 + A1*B3 - A3*B1 + A4*B6 - A6*B4 - A2*B7 - A7*B2;
    // e23
    float o6 = A0*B6 + A6*B0 + A2*B3 - A3*B2 - A4*B5 + A5*B4 + A1*B7 + A7*B1;
    // e123
    float o7 = A0*B7 + A7*B0 + A1*B6 + A6*B1 - A2*B5 - A5*B2 + A3*B4 + A4*B3;

    out4[2 * t + 0] = make_float4(o0, o1, o2, o3);
    out4[2 * t + 1] = make_float4(o4v, o5, o6, o7);
}

extern "C" void kernel_launch(void* const* d_in, const int* in_sizes, int n_in,
                              void* d_out, int out_size)
{
    const float4* a = (const float4*)d_in[0];
    const float4* b = (const float4*)d_in[1];
    // d_in[2] = cayley table, constant for metric [1,1,1]; hardcoded above.
    float4* out = (float4*)d_out;

    int n_mv = in_sizes[0] / 8;  // 65536 * 64 = 4,194,304 multivectors
    int threads = 256;
    int blocks = (n_mv + threads - 1) / threads;
    clifford_gp_kernel<<<blocks, threads>>>(a, b, out, n_mv);
}